// round 16
// baseline (speedup 1.0000x reference)
#include <cuda_runtime.h>
#include <cuda_bf16.h>
#include <math.h>
#include <stdint.h>

#define D_MODEL 1024
#define NHEADS  16
#define DK      64
#define SEQ     2048
#define BATCH   2
#define NTOK    (BATCH*SEQ)   // 4096
#define DFF     4096

// ---------------- scratch (no allocations allowed) ----------------
__device__ float g_s1 [NTOK*D_MODEL];
__device__ float g_x1 [NTOK*D_MODEL];
__device__ float g_s2 [NTOK*D_MODEL];

// bf16 hi/lo operand arrays
__device__ __nv_bfloat16 g_xh  [NTOK*D_MODEL];   __device__ __nv_bfloat16 g_xl  [NTOK*D_MODEL];
__device__ __nv_bfloat16 g_qkvh[3*NTOK*D_MODEL]; __device__ __nv_bfloat16 g_qkvl[3*NTOK*D_MODEL];
__device__ __nv_bfloat16 g_ctxh[NTOK*D_MODEL];   __device__ __nv_bfloat16 g_ctxl[NTOK*D_MODEL];
__device__ __nv_bfloat16 g_x1h [NTOK*D_MODEL];   __device__ __nv_bfloat16 g_x1l [NTOK*D_MODEL];
__device__ __nv_bfloat16 g_ffh [NTOK*DFF];       __device__ __nv_bfloat16 g_ffl [NTOK*DFF];

// pre-split transposed weights [N][K], bf16 hi/lo
__device__ __nv_bfloat16 g_wqkv_hi[3*D_MODEL*D_MODEL];
__device__ __nv_bfloat16 g_wqkv_lo[3*D_MODEL*D_MODEL];
__device__ __nv_bfloat16 g_wo_hi  [D_MODEL*D_MODEL];
__device__ __nv_bfloat16 g_wo_lo  [D_MODEL*D_MODEL];
__device__ __nv_bfloat16 g_w1_hi  [DFF*D_MODEL];
__device__ __nv_bfloat16 g_w1_lo  [DFF*D_MODEL];
__device__ __nv_bfloat16 g_w2_hi  [D_MODEL*DFF];
__device__ __nv_bfloat16 g_w2_lo  [D_MODEL*DFF];

// ---------------- helpers ----------------
__device__ __forceinline__ uint32_t smem_u32(const void* p) {
    uint32_t a;
    asm("{ .reg .u64 t; cvta.to.shared.u64 t, %1; cvt.u32.u64 %0, t; }" : "=r"(a) : "l"(p));
    return a;
}
__device__ __forceinline__ void ldsm4(uint32_t* r, uint32_t addr) {
    asm volatile("ldmatrix.sync.aligned.m8n8.x4.shared.b16 {%0,%1,%2,%3}, [%4];"
        : "=r"(r[0]), "=r"(r[1]), "=r"(r[2]), "=r"(r[3]) : "r"(addr));
}
__device__ __forceinline__ void ldsm4t(uint32_t* r, uint32_t addr) {
    asm volatile("ldmatrix.sync.aligned.m8n8.x4.trans.shared.b16 {%0,%1,%2,%3}, [%4];"
        : "=r"(r[0]), "=r"(r[1]), "=r"(r[2]), "=r"(r[3]) : "r"(addr));
}
__device__ __forceinline__ void mma_bf16(float* d, const uint32_t* a, const uint32_t* b) {
    asm volatile(
        "mma.sync.aligned.m16n8k16.row.col.f32.bf16.bf16.f32 "
        "{%0,%1,%2,%3}, {%4,%5,%6,%7}, {%8,%9}, {%0,%1,%2,%3};"
        : "+f"(d[0]), "+f"(d[1]), "+f"(d[2]), "+f"(d[3])
        : "r"(a[0]), "r"(a[1]), "r"(a[2]), "r"(a[3]), "r"(b[0]), "r"(b[1]));
}
__device__ __forceinline__ uint32_t packbf2(float x, float y) {
    __nv_bfloat162 h = __floats2bfloat162_rn(x, y);
    return *(uint32_t*)&h;
}
__device__ __forceinline__ uint32_t packbf16pair(__nv_bfloat16 a, __nv_bfloat16 b) {
    return (uint32_t)__bfloat16_as_ushort(a) | ((uint32_t)__bfloat16_as_ushort(b) << 16);
}
__device__ __forceinline__ float fexp(float x) {
    float y = x * 1.4426950408889634f;
    y = fmaxf(y, -126.0f);
    float t = y + 12582912.0f;
    int   n = __float_as_int(t) - 0x4B400000;
    float f = y - (t - 12582912.0f);
    float p = 1.3333558146428443e-3f;
    p = fmaf(p, f, 9.6181291076284772e-3f);
    p = fmaf(p, f, 5.5504108664821580e-2f);
    p = fmaf(p, f, 2.4022650695910072e-1f);
    p = fmaf(p, f, 6.9314718055994531e-1f);
    p = fmaf(p, f, 1.0f);
    return __int_as_float(__float_as_int(p) + (n << 23));
}
__device__ __forceinline__ void split_pair(float v0, float v1, uint32_t& hp, uint32_t& lp) {
    __nv_bfloat16 h0 = __float2bfloat16(v0), h1 = __float2bfloat16(v1);
    hp = packbf16pair(h0, h1);
    lp = packbf2(v0 - __bfloat162float(h0), v1 - __bfloat162float(h1));
}

// ---------------- elementwise fp32 -> bf16 hi/lo split ----------------
__global__ __launch_bounds__(256)
void xsplit(const float* __restrict__ A, __nv_bfloat16* __restrict__ H,
            __nv_bfloat16* __restrict__ L)
{
    const size_t i = ((size_t)blockIdx.x * 256 + threadIdx.x) * 4;
    float4 v = *(const float4*)(A + i);
    uint32_t h0, l0, h1, l1;
    split_pair(v.x, v.y, h0, l0);
    split_pair(v.z, v.w, h1, l1);
    *(uint2*)(H + i) = make_uint2(h0, h1);
    *(uint2*)(L + i) = make_uint2(l0, l1);
}

// ---------------- weight prep: W[K][N] fp32 -> T[N][K] bf16 hi/lo ----------------
__global__ void prep_w(const float* __restrict__ W, __nv_bfloat16* __restrict__ Thi,
                       __nv_bfloat16* __restrict__ Tlo, int K, int N)
{
    __shared__ float t[32][33];
    const int k0 = blockIdx.y * 32, n0 = blockIdx.x * 32;
    const int tx = threadIdx.x, ty = threadIdx.y;
#pragma unroll
    for (int r = 0; r < 4; r++)
        t[ty + 8*r][tx] = W[(size_t)(k0 + ty + 8*r) * N + n0 + tx];
    __syncthreads();
#pragma unroll
    for (int r = 0; r < 4; r++) {
        const int n = n0 + ty + 8*r, k = k0 + tx;
        float x = t[tx][ty + 8*r];
        __nv_bfloat16 hi = __float2bfloat16(x);
        __nv_bfloat16 lo = __float2bfloat16(x - __bfloat162float(hi));
        Thi[(size_t)n * K + k] = hi;
        Tlo[(size_t)n * K + k] = lo;
    }
}

// ---------------- bf16x3 mma.sync GEMM, 16 warps (4m x 4n), 4-stage ring ----------------
// C[M,N] = (Ahi+Alo)[M,K] @ (Bhi+Blo)[N,K]^T  via hh+hl+lh
// Block 128x128, BK=32, 512 threads, warp tile 32x32 -> 4 warps/SMSP for latency hiding.
// smem per stage: Ah/Al/Bh/Bl each [128 rows][32 bf16] pad 80B = 10240B -> 40960B
#define GS_BUF   40960
#define SMEM_G   (4*GS_BUF)

template<int EPI>
__global__ __launch_bounds__(512, 1)
void bf16_gemm(const __nv_bfloat16* __restrict__ Ahi, const __nv_bfloat16* __restrict__ Alo,
               const __nv_bfloat16* __restrict__ Bhi, const __nv_bfloat16* __restrict__ Blo,
               float* __restrict__ C, const float* __restrict__ bias,
               const float* __restrict__ res, int N, int K,
               __nv_bfloat16* __restrict__ Ohi, __nv_bfloat16* __restrict__ Olo)
{
    extern __shared__ char smem[];
    const uint32_t sbase = smem_u32(smem);
    const int tid = threadIdx.x, wid = tid >> 5, lane = tid & 31;
    const int g = lane >> 2, t = lane & 3;
    const int wm = wid >> 2, wn = wid & 3;       // 4 x 4 warp grid
    const int bm = blockIdx.y, bn = blockIdx.x;

    float c[2][4][4];
#pragma unroll
    for (int mt = 0; mt < 2; mt++)
#pragma unroll
        for (int nt = 0; nt < 4; nt++)
#pragma unroll
            for (int f = 0; f < 4; f++) c[mt][nt][f] = 0.f;

    auto cp_all = [&](int buf, int kb) {
#pragma unroll
        for (int j = 0; j < 4; j++) {
            const int cidx = tid + 512 * j;
            const int arr = cidx >> 9;      // 0:Ah 1:Al 2:Bh 3:Bl
            const int cc  = cidx & 511;
            const int row = cc >> 2, kc = cc & 3;
            const __nv_bfloat16* gp = (arr == 0 ? Ahi : arr == 1 ? Alo : arr == 2 ? Bhi : Blo);
            const int base = (arr < 2 ? bm : bn) * 128;
            const __nv_bfloat16* src = gp + (size_t)(base + row) * K + kb * 32 + kc * 8;
            const uint32_t dst = sbase + buf * GS_BUF + arr * 10240 + row * 80 + kc * 16;
            asm volatile("cp.async.cg.shared.global [%0], [%1], 16;\n" :: "r"(dst), "l"(src));
        }
        asm volatile("cp.async.commit_group;\n");
    };

    const uint32_t a_off = (uint32_t)((wm * 32 + (lane & 15)) * 80 + ((lane >> 4) << 4));
    const uint32_t b_off = (uint32_t)((wn * 32 + ((lane >> 4) << 3) + (lane & 7)) * 80
                                      + (((lane >> 3) & 1) << 4));

    const int niter = K >> 5;
    cp_all(0, 0);
    if (niter > 1) cp_all(1, 1);
    if (niter > 2) cp_all(2, 2);

    for (int it = 0; it < niter; it++) {
        const int buf = it & 3;
        asm volatile("cp.async.wait_group 2;\n");
        __syncthreads();
        if (it + 3 < niter) cp_all((it + 3) & 3, it + 3);

        const uint32_t sb = sbase + buf * GS_BUF;
#pragma unroll
        for (int ks = 0; ks < 2; ks++) {
            uint32_t Ah[2][4], Al[2][4], Bh[2][4], Bl[2][4];
#pragma unroll
            for (int mt = 0; mt < 2; mt++) {
                const uint32_t aa = sb + a_off + mt * (16 * 80) + ks * 32;
                ldsm4(Ah[mt], aa);
                ldsm4(Al[mt], aa + 10240);
            }
#pragma unroll
            for (int ng = 0; ng < 2; ng++) {
                const uint32_t ba = sb + b_off + ng * (16 * 80) + ks * 32;
                ldsm4(Bh[ng], ba + 20480);
                ldsm4(Bl[ng], ba + 30720);
            }
#pragma unroll
            for (int mt = 0; mt < 2; mt++)
#pragma unroll
                for (int nt = 0; nt < 4; nt++) {
                    const uint32_t* bh = &Bh[nt >> 1][(nt & 1) * 2];
                    const uint32_t* bl = &Bl[nt >> 1][(nt & 1) * 2];
                    mma_bf16(c[mt][nt], Ah[mt], bh);   // hi*hi
                    mma_bf16(c[mt][nt], Ah[mt], bl);   // hi*lo
                    mma_bf16(c[mt][nt], Al[mt], bh);   // lo*hi
                }
        }
    }

    // ---------------- epilogue ----------------
#pragma unroll
    for (int mt = 0; mt < 2; mt++) {
        const int r0 = bm * 128 + wm * 32 + mt * 16 + g;
#pragma unroll
        for (int nt = 0; nt < 4; nt++) {
            const int c0 = bn * 128 + wn * 32 + nt * 8 + t * 2;
#pragma unroll
            for (int half = 0; half < 2; half++) {
                const int r = r0 + half * 8;
                float v0 = c[mt][nt][half * 2], v1 = c[mt][nt][half * 2 + 1];
                if (EPI == 1) {
                    const int which = c0 >> 10, cm = c0 & 1023;
                    if (which == 0) { v0 *= 0.125f; v1 *= 0.125f; }
                    uint32_t hp, lp;
                    split_pair(v0, v1, hp, lp);
                    const size_t idx = (size_t)which * (NTOK * D_MODEL)
                        + (((size_t)((r >> 11) * NHEADS + (cm >> 6)) * SEQ + (r & 2047)) * DK + (cm & 63));
                    *(uint32_t*)(Ohi + idx) = hp;
                    *(uint32_t*)(Olo + idx) = lp;
                } else if (EPI == 2) {
                    const float* rs = res + (size_t)r * N + c0;
                    C[(size_t)r * N + c0]     = v0 + bias[c0]     + rs[0];
                    C[(size_t)r * N + c0 + 1] = v1 + bias[c0 + 1] + rs[1];
                } else { // 3: relu -> bf16 hi/lo
                    float a0 = fmaxf(v0 + bias[c0], 0.f);
                    float a1 = fmaxf(v1 + bias[c0 + 1], 0.f);
                    uint32_t hp, lp;
                    split_pair(a0, a1, hp, lp);
                    const size_t idx = (size_t)r * N + c0;
                    *(uint32_t*)(Ohi + idx) = hp;
                    *(uint32_t*)(Olo + idx) = lp;
                }
            }
        }
    }
}

// ---------------- FA2-style tensor-core attention (proven; bf16 ctx out) ----------------
#define AQ_H   0
#define AQ_L   18432
#define AKV    36864
#define AKVBUF 36864
#define ATSMEM (36864 + 2*36864)

__global__ __launch_bounds__(256, 2)
void attn_mma(const __nv_bfloat16* __restrict__ qkvh, const __nv_bfloat16* __restrict__ qkvl,
              const int* __restrict__ mask,
              __nv_bfloat16* __restrict__ ctxh, __nv_bfloat16* __restrict__ ctxl)
{
    extern __shared__ char sm[];
    const uint32_t sb = smem_u32(sm);
    const int tid = threadIdx.x, w = tid >> 5, lane = tid & 31;
    const int g = lane >> 2, t = lane & 3;
    const int qb = blockIdx.x, h = blockIdx.y, b = blockIdx.z;
    const size_t hoff = ((size_t)(b * NHEADS + h)) * SEQ * DK;

    const __nv_bfloat16* qh = qkvh + hoff + (size_t)qb * 128 * DK;
    const __nv_bfloat16* ql = qkvl + hoff + (size_t)qb * 128 * DK;
    const __nv_bfloat16* kh = qkvh + (size_t)NTOK * D_MODEL + hoff;
    const __nv_bfloat16* kl = qkvl + (size_t)NTOK * D_MODEL + hoff;
    const __nv_bfloat16* vh = qkvh + (size_t)2 * NTOK * D_MODEL + hoff;
    const __nv_bfloat16* vl = qkvl + (size_t)2 * NTOK * D_MODEL + hoff;

#pragma unroll
    for (int j = 0; j < 8; j++) {
        const int cidx = tid + j * 256;
        const int arr = cidx >> 10, cc = cidx & 1023;
        const int row = cc >> 3, k8 = cc & 7;
        const __nv_bfloat16* src = (arr == 0 ? qh : ql) + row * DK + k8 * 8;
        *(uint4*)(sm + AQ_H + arr * 18432 + row * 144 + k8 * 16) = *(const uint4*)src;
    }

    auto prefetch_kv = [&](int buf, int kv0) {
#pragma unroll
        for (int j = 0; j < 8; j++) {
            const int cidx = tid + j * 256;
            const int arr = cidx >> 9, cc = cidx & 511;
            const int row = cc >> 3, k8 = cc & 7;
            const __nv_bfloat16* src =
                (arr == 0 ? kh : arr == 1 ? kl : arr == 2 ? vh : vl)
                + (size_t)(kv0 + row) * DK + k8 * 8;
            const uint32_t dst = sb + AKV + buf * AKVBUF + arr * 9216 + row * 144 + k8 * 16;
            asm volatile("cp.async.cg.shared.global [%0], [%1], 16;\n" :: "r"(dst), "l"(src));
        }
        asm volatile("cp.async.commit_group;\n");
    };

    prefetch_kv(0, 0);

    float m0 = -1e30f, m1 = -1e30f, l0 = 0.f, l1 = 0.f;
    float co[8][4];
#pragma unroll
    for (int nt = 0; nt < 8; nt++)
#pragma unroll
        for (int f = 0; f < 4; f++) co[nt][f] = 0.f;

    const uint32_t qa_off = (uint32_t)((w * 16 + (lane & 15)) * 144 + ((lane >> 4) << 4));
    const uint32_t kb_sub = (uint32_t)((((lane >> 4) << 3) + (lane & 7)) * 144
                                       + (((lane >> 3) & 1) << 4));
    const uint32_t vb_sub = (uint32_t)(((((lane >> 3) & 1) << 3) + (lane & 7)) * 144
                                       + ((lane >> 4) << 4));
    const int* mrow_base = mask + b * SEQ;

    for (int it = 0; it < SEQ / 64; it++) {
        const int buf = it & 1;
        const int kv0 = it * 64;
        asm volatile("cp.async.wait_group 0;\n");
        __syncthreads();
        if (it + 1 < SEQ / 64) prefetch_kv(buf ^ 1, kv0 + 64);

        const uint32_t kvb = sb + AKV + buf * AKVBUF;

        float cs[8][4];
#pragma unroll
        for (int nt = 0; nt < 8; nt++)
#pragma unroll
            for (int f = 0; f < 4; f++) cs[nt][f] = 0.f;
#pragma unroll
        for (int ks = 0; ks < 4; ks++) {
            uint32_t Qh_[4], Ql_[4];
            const uint32_t aa = sb + qa_off + ks * 32;
            ldsm4(Qh_, aa + AQ_H);
            ldsm4(Ql_, aa + AQ_L);
#pragma unroll
            for (int ng = 0; ng < 4; ng++) {
                uint32_t Kh_[4], Kl_[4];
                const uint32_t ba = kvb + ng * (16 * 144) + kb_sub + ks * 32;
                ldsm4(Kh_, ba);
                ldsm4(Kl_, ba + 9216);
#pragma unroll
                for (int h2 = 0; h2 < 2; h2++) {
                    const int nt = ng * 2 + h2;
                    mma_bf16(cs[nt], Qh_, &Kh_[h2 * 2]);
                    mma_bf16(cs[nt], Qh_, &Kl_[h2 * 2]);
                    mma_bf16(cs[nt], Ql_, &Kh_[h2 * 2]);
                }
            }
        }

#pragma unroll
        for (int nt = 0; nt < 8; nt++) {
            int2 mv = *(const int2*)(mrow_base + kv0 + nt * 8 + t * 2);
            if (mv.x == 0) { cs[nt][0] = -1e9f; cs[nt][2] = -1e9f; }
            if (mv.y == 0) { cs[nt][1] = -1e9f; cs[nt][3] = -1e9f; }
        }
        float mx0 = cs[0][0], mx1 = cs[0][2];
#pragma unroll
        for (int nt = 0; nt < 8; nt++) {
            mx0 = fmaxf(mx0, fmaxf(cs[nt][0], cs[nt][1]));
            mx1 = fmaxf(mx1, fmaxf(cs[nt][2], cs[nt][3]));
        }
        mx0 = fmaxf(mx0, __shfl_xor_sync(0xffffffffu, mx0, 1));
        mx0 = fmaxf(mx0, __shfl_xor_sync(0xffffffffu, mx0, 2));
        mx1 = fmaxf(mx1, __shfl_xor_sync(0xffffffffu, mx1, 1));
        mx1 = fmaxf(mx1, __shfl_xor_sync(0xffffffffu, mx1, 2));
        const float mn0 = fmaxf(m0, mx0), mn1 = fmaxf(m1, mx1);
        const float f0 = fexp(m0 - mn0), f1 = fexp(m1 - mn1);
        m0 = mn0; m1 = mn1;

        uint32_t phg[8], phg8[8], plg[8], plg8[8];
        float rs0 = 0.f, rs1 = 0.f;
#pragma unroll
        for (int nt = 0; nt < 8; nt++) {
            float p0 = fexp(cs[nt][0] - mn0);
            float p1 = fexp(cs[nt][1] - mn0);
            float p2 = fexp(cs[nt][2] - mn1);
            float p3 = fexp(cs[nt][3] - mn1);
            rs0 += p0 + p1; rs1 += p2 + p3;
            split_pair(p0, p1, phg[nt], plg[nt]);
            split_pair(p2, p3, phg8[nt], plg8[nt]);
        }
        rs0 += __shfl_xor_sync(0xffffffffu, rs0, 1);
        rs0 += __shfl_xor_sync(0xffffffffu, rs0, 2);
        rs1 += __shfl_xor_sync(0xffffffffu, rs1, 1);
        rs1 += __shfl_xor_sync(0xffffffffu, rs1, 2);
        l0 = l0 * f0 + rs0;
        l1 = l1 * f1 + rs1;

#pragma unroll
        for (int nt = 0; nt < 8; nt++) {
            co[nt][0] *= f0; co[nt][1] *= f0;
            co[nt][2] *= f1; co[nt][3] *= f1;
        }

#pragma unroll
        for (int kc = 0; kc < 4; kc++) {
            uint32_t Ah[4] = { phg[2*kc], phg8[2*kc], phg[2*kc+1], phg8[2*kc+1] };
            uint32_t Al[4] = { plg[2*kc], plg8[2*kc], plg[2*kc+1], plg8[2*kc+1] };
#pragma unroll
            for (int ng = 0; ng < 4; ng++) {
                uint32_t Vh_[4], Vl_[4];
                const uint32_t va = kvb + 18432 + kc * (16 * 144) + vb_sub + ng * 32;
                ldsm4t(Vh_, va);
                ldsm4t(Vl_, va + 9216);
#pragma unroll
                for (int h2 = 0; h2 < 2; h2++) {
                    const int nt = ng * 2 + h2;
                    mma_bf16(co[nt], Ah, &Vh_[h2 * 2]);
                    mma_bf16(co[nt], Ah, &Vl_[h2 * 2]);
                    mma_bf16(co[nt], Al, &Vh_[h2 * 2]);
                }
            }
        }
    }

    const float inv0 = 1.0f / l0, inv1 = 1.0f / l1;
    const int r0 = qb * 128 + w * 16 + g;
    const size_t base0 = ((size_t)(b * SEQ + r0)) * D_MODEL + h * 64;
    const size_t base1 = ((size_t)(b * SEQ + r0 + 8)) * D_MODEL + h * 64;
#pragma unroll
    for (int nt = 0; nt < 8; nt++) {
        const int col = nt * 8 + t * 2;
        uint32_t hp, lp;
        split_pair(co[nt][0] * inv0, co[nt][1] * inv0, hp, lp);
        *(uint32_t*)(ctxh + base0 + col) = hp;
        *(uint32_t*)(ctxl + base0 + col) = lp;
        split_pair(co[nt][2] * inv1, co[nt][3] * inv1, hp, lp);
        *(uint32_t*)(ctxh + base1 + col) = hp;
        *(uint32_t*)(ctxl + base1 + col) = lp;
    }
}

// ---------------- LayerNorm (ddof=1, eps added to std); optional bf16 hi/lo out ----------------
__device__ __forceinline__ float warp_sum(float s) {
#pragma unroll
    for (int off = 16; off; off >>= 1) s += __shfl_xor_sync(0xffffffffu, s, off);
    return s;
}

__global__ __launch_bounds__(256)
void ln_kernel(const float* __restrict__ in, const float* __restrict__ alpha,
               const float* __restrict__ beta, float* __restrict__ out,
               __nv_bfloat16* __restrict__ outh, __nv_bfloat16* __restrict__ outl)
{
    __shared__ float red[8];
    const int row = blockIdx.x, tid = threadIdx.x;
    const float* rp = in + (size_t)row * D_MODEL;
    float4 v = *(const float4*)(rp + tid*4);

    float s = v.x + v.y + v.z + v.w;
    s = warp_sum(s);
    if ((tid & 31) == 0) red[tid >> 5] = s;
    __syncthreads();
    float tot = 0.f;
#pragma unroll
    for (int i = 0; i < 8; i++) tot += red[i];
    float mean = tot * (1.0f / 1024.0f);

    float dx = v.x - mean, dy = v.y - mean, dz = v.z - mean, dw = v.w - mean;
    float sq = dx*dx + dy*dy + dz*dz + dw*dw;
    __syncthreads();
    sq = warp_sum(sq);
    if ((tid & 31) == 0) red[tid >> 5] = sq;
    __syncthreads();
    float tot2 = 0.f;
#pragma unroll
    for (int i = 0; i < 8; i++) tot2 += red[i];
    float var  = tot2 * (1.0f / 1023.0f);
    float rstd = 1.0f / (sqrtf(var) + 1e-6f);

    float4 a = *(const float4*)(alpha + tid*4);
    float4 bb = *(const float4*)(beta + tid*4);
    float4 o;
    o.x = a.x * dx * rstd + bb.x;
    o.y = a.y * dy * rstd + bb.y;
    o.z = a.z * dz * rstd + bb.z;
    o.w = a.w * dw * rstd + bb.w;
    *(float4*)(out + (size_t)row * D_MODEL + tid*4) = o;
    if (outh) {
        uint32_t h0, l0, h1, l1;
        split_pair(o.x, o.y, h0, l0);
        split_pair(o.z, o.w, h1, l1);
        *(uint2*)(outh + (size_t)row * D_MODEL + tid*4) = make_uint2(h0, h1);
        *(uint2*)(outl + (size_t)row * D_MODEL + tid*4) = make_uint2(l0, l1);
    }
}

// ---------------- host ----------------
extern "C" void kernel_launch(void* const* d_in, const int* in_sizes, int n_in,
                              void* d_out, int out_size)
{
    const float* x      = (const float*)d_in[0];
    const int*   mask   = (const int*)  d_in[1];
    const float* wq     = (const float*)d_in[2];
    const float* wk     = (const float*)d_in[3];
    const float* wv     = (const float*)d_in[4];
    const float* wo     = (const float*)d_in[5];
    const float* wo_b   = (const float*)d_in[6];
    const float* w1     = (const float*)d_in[7];
    const float* b1     = (const float*)d_in[8];
    const float* w2     = (const float*)d_in[9];
    const float* b2     = (const float*)d_in[10];
    const float* alpha1 = (const float*)d_in[11];
    const float* bias1  = (const float*)d_in[12];
    const float* alpha2 = (const float*)d_in[13];
    const float* bias2  = (const float*)d_in[14];
    float* out = (float*)d_out;

    float *s1, *x1, *s2;
    __nv_bfloat16 *xh, *xl, *qkvh, *qkvl, *ctxh, *ctxl, *x1h, *x1l, *ffh, *ffl;
    __nv_bfloat16 *wqkv_hi, *wqkv_lo, *wo_hi, *wo_lo, *w1_hi, *w1_lo, *w2_hi, *w2_lo;
    cudaGetSymbolAddress((void**)&s1,  g_s1);
    cudaGetSymbolAddress((void**)&x1,  g_x1);
    cudaGetSymbolAddress((void**)&s2,  g_s2);
    cudaGetSymbolAddress((void**)&xh,  g_xh);   cudaGetSymbolAddress((void**)&xl,  g_xl);
    cudaGetSymbolAddress((void**)&qkvh, g_qkvh); cudaGetSymbolAddress((void**)&qkvl, g_qkvl);
    cudaGetSymbolAddress((void**)&ctxh, g_ctxh); cudaGetSymbolAddress((void**)&ctxl, g_ctxl);
    cudaGetSymbolAddress((void**)&x1h, g_x1h);  cudaGetSymbolAddress((void**)&x1l, g_x1l);
    cudaGetSymbolAddress((void**)&ffh, g_ffh);  cudaGetSymbolAddress((void**)&ffl, g_ffl);
    cudaGetSymbolAddress((void**)&wqkv_hi, g_wqkv_hi);
    cudaGetSymbolAddress((void**)&wqkv_lo, g_wqkv_lo);
    cudaGetSymbolAddress((void**)&wo_hi, g_wo_hi);
    cudaGetSymbolAddress((void**)&wo_lo, g_wo_lo);
    cudaGetSymbolAddress((void**)&w1_hi, g_w1_hi);
    cudaGetSymbolAddress((void**)&w1_lo, g_w1_lo);
    cudaGetSymbolAddress((void**)&w2_hi, g_w2_hi);
    cudaGetSymbolAddress((void**)&w2_lo, g_w2_lo);

    // idempotent; no static guards allowed
    cudaFuncSetAttribute(bf16_gemm<1>, cudaFuncAttributeMaxDynamicSharedMemorySize, SMEM_G);
    cudaFuncSetAttribute(bf16_gemm<2>, cudaFuncAttributeMaxDynamicSharedMemorySize, SMEM_G);
    cudaFuncSetAttribute(bf16_gemm<3>, cudaFuncAttributeMaxDynamicSharedMemorySize, SMEM_G);
    cudaFuncSetAttribute(attn_mma,     cudaFuncAttributeMaxDynamicSharedMemorySize, ATSMEM);

    dim3 tblk(32, 8);
    prep_w<<<dim3(D_MODEL/32, D_MODEL/32), tblk>>>(wq, wqkv_hi,                     wqkv_lo,                     D_MODEL, D_MODEL);
    prep_w<<<dim3(D_MODEL/32, D_MODEL/32), tblk>>>(wk, wqkv_hi + D_MODEL*D_MODEL,   wqkv_lo + D_MODEL*D_MODEL,   D_MODEL, D_MODEL);
    prep_w<<<dim3(D_MODEL/32, D_MODEL/32), tblk>>>(wv, wqkv_hi + 2*D_MODEL*D_MODEL, wqkv_lo + 2*D_MODEL*D_MODEL, D_MODEL, D_MODEL);
    prep_w<<<dim3(D_MODEL/32, D_MODEL/32), tblk>>>(wo, wo_hi, wo_lo, D_MODEL, D_MODEL);
    prep_w<<<dim3(DFF/32,     D_MODEL/32), tblk>>>(w1, w1_hi, w1_lo, D_MODEL, DFF);
    prep_w<<<dim3(D_MODEL/32, DFF/32),     tblk>>>(w2, w2_hi, w2_lo, DFF, D_MODEL);

    // split x once
    xsplit<<<(NTOK*D_MODEL)/1024, 256>>>(x, xh, xl);

    // fused QKV projection (N=3072) -> bf16 hi/lo head-transposed, q pre-scaled
    bf16_gemm<1><<<dim3(24, 32), 512, SMEM_G>>>(xh, xl, wqkv_hi, wqkv_lo,
                                                nullptr, nullptr, nullptr, 3*D_MODEL, D_MODEL, qkvh, qkvl);

    attn_mma<<<dim3(SEQ/128, NHEADS, BATCH), 256, ATSMEM>>>(qkvh, qkvl, mask, ctxh, ctxl);

    // O projection + residual, LN1 (emits bf16 for FFN1 A)
    bf16_gemm<2><<<dim3(8, 32), 512, SMEM_G>>>(ctxh, ctxl, wo_hi, wo_lo,
                                               s1, wo_b, x, D_MODEL, D_MODEL, nullptr, nullptr);
    ln_kernel<<<NTOK, 256>>>(s1, alpha1, bias1, x1, x1h, x1l);

    // FFN
    bf16_gemm<3><<<dim3(32, 32), 512, SMEM_G>>>(x1h, x1l, w1_hi, w1_lo,
                                                nullptr, b1, nullptr, DFF, D_MODEL, ffh, ffl);
    bf16_gemm<2><<<dim3(8, 32), 512, SMEM_G>>>(ffh, ffl, w2_hi, w2_lo,
                                               s2, b2, x1, D_MODEL, DFF, nullptr, nullptr);
    ln_kernel<<<NTOK, 256>>>(s2, alpha2, bias2, out, nullptr, nullptr);
}

// round 17
// speedup vs baseline: 1.2724x; 1.2724x over previous
#include <cuda_runtime.h>
#include <cuda_bf16.h>
#include <cuda_fp16.h>
#include <math.h>
#include <stdint.h>

#define D_MODEL 1024
#define NHEADS  16
#define DK      64
#define SEQ     2048
#define BATCH   2
#define NTOK    (BATCH*SEQ)   // 4096
#define DFF     4096

// ---------------- scratch (no allocations allowed) ----------------
__device__ float g_s1 [NTOK*D_MODEL];
__device__ float g_x1 [NTOK*D_MODEL];
__device__ float g_s2 [NTOK*D_MODEL];

// fp16 hi/lo activation operands (A side of GEMMs)
__device__ __half g_xh  [NTOK*D_MODEL];   __device__ __half g_xl  [NTOK*D_MODEL];
__device__ __half g_ctxh[NTOK*D_MODEL];   __device__ __half g_ctxl[NTOK*D_MODEL];
__device__ __half g_x1h [NTOK*D_MODEL];   __device__ __half g_x1l [NTOK*D_MODEL];
__device__ __half g_ffh [NTOK*DFF];       __device__ __half g_ffl [NTOK*DFF];

// attention operands (bf16 hi/lo, q pre-scaled by 1/8)
__device__ __nv_bfloat16 g_qkvh[3*NTOK*D_MODEL];
__device__ __nv_bfloat16 g_qkvl[3*NTOK*D_MODEL];

// single-fp16 transposed weights [N][K]
__device__ __half g_wqkv_f[3*D_MODEL*D_MODEL];
__device__ __half g_wo_f  [D_MODEL*D_MODEL];
__device__ __half g_w1_f  [DFF*D_MODEL];
__device__ __half g_w2_f  [D_MODEL*DFF];

// ---------------- helpers ----------------
__device__ __forceinline__ uint32_t smem_u32(const void* p) {
    uint32_t a;
    asm("{ .reg .u64 t; cvta.to.shared.u64 t, %1; cvt.u32.u64 %0, t; }" : "=r"(a) : "l"(p));
    return a;
}
__device__ __forceinline__ void ldsm4(uint32_t* r, uint32_t addr) {
    asm volatile("ldmatrix.sync.aligned.m8n8.x4.shared.b16 {%0,%1,%2,%3}, [%4];"
        : "=r"(r[0]), "=r"(r[1]), "=r"(r[2]), "=r"(r[3]) : "r"(addr));
}
__device__ __forceinline__ void ldsm4t(uint32_t* r, uint32_t addr) {
    asm volatile("ldmatrix.sync.aligned.m8n8.x4.trans.shared.b16 {%0,%1,%2,%3}, [%4];"
        : "=r"(r[0]), "=r"(r[1]), "=r"(r[2]), "=r"(r[3]) : "r"(addr));
}
__device__ __forceinline__ void mma_bf16(float* d, const uint32_t* a, const uint32_t* b) {
    asm volatile(
        "mma.sync.aligned.m16n8k16.row.col.f32.bf16.bf16.f32 "
        "{%0,%1,%2,%3}, {%4,%5,%6,%7}, {%8,%9}, {%0,%1,%2,%3};"
        : "+f"(d[0]), "+f"(d[1]), "+f"(d[2]), "+f"(d[3])
        : "r"(a[0]), "r"(a[1]), "r"(a[2]), "r"(a[3]), "r"(b[0]), "r"(b[1]));
}
__device__ __forceinline__ void mma_f16(float* d, const uint32_t* a, const uint32_t* b) {
    asm volatile(
        "mma.sync.aligned.m16n8k16.row.col.f32.f16.f16.f32 "
        "{%0,%1,%2,%3}, {%4,%5,%6,%7}, {%8,%9}, {%0,%1,%2,%3};"
        : "+f"(d[0]), "+f"(d[1]), "+f"(d[2]), "+f"(d[3])
        : "r"(a[0]), "r"(a[1]), "r"(a[2]), "r"(a[3]), "r"(b[0]), "r"(b[1]));
}
__device__ __forceinline__ uint32_t packbf2(float x, float y) {
    __nv_bfloat162 h = __floats2bfloat162_rn(x, y);
    return *(uint32_t*)&h;
}
__device__ __forceinline__ uint32_t packbf16pair(__nv_bfloat16 a, __nv_bfloat16 b) {
    return (uint32_t)__bfloat16_as_ushort(a) | ((uint32_t)__bfloat16_as_ushort(b) << 16);
}
__device__ __forceinline__ float fexp(float x) {
    float y = x * 1.4426950408889634f;
    y = fmaxf(y, -126.0f);
    float t = y + 12582912.0f;
    int   n = __float_as_int(t) - 0x4B400000;
    float f = y - (t - 12582912.0f);
    float p = 1.3333558146428443e-3f;
    p = fmaf(p, f, 9.6181291076284772e-3f);
    p = fmaf(p, f, 5.5504108664821580e-2f);
    p = fmaf(p, f, 2.4022650695910072e-1f);
    p = fmaf(p, f, 6.9314718055994531e-1f);
    p = fmaf(p, f, 1.0f);
    return __int_as_float(__float_as_int(p) + (n << 23));
}
// bf16 hi/lo pair split (attention path)
__device__ __forceinline__ void split_pair(float v0, float v1, uint32_t& hp, uint32_t& lp) {
    __nv_bfloat16 h0 = __float2bfloat16(v0), h1 = __float2bfloat16(v1);
    hp = packbf16pair(h0, h1);
    lp = packbf2(v0 - __bfloat162float(h0), v1 - __bfloat162float(h1));
}
// fp16 hi/lo pair split (GEMM A path)
__device__ __forceinline__ void split_pair_f16(float v0, float v1, uint32_t& hp, uint32_t& lp) {
    __half h0 = __float2half_rn(v0), h1 = __float2half_rn(v1);
    __half2 hh = __halves2half2(h0, h1);
    __half2 ll = __floats2half2_rn(v0 - __half2float(h0), v1 - __half2float(h1));
    hp = *(uint32_t*)&hh;
    lp = *(uint32_t*)&ll;
}

// ---------------- elementwise fp32 -> fp16 hi/lo split ----------------
__global__ __launch_bounds__(256)
void xsplit(const float* __restrict__ A, __half* __restrict__ H, __half* __restrict__ L)
{
    const size_t i = ((size_t)blockIdx.x * 256 + threadIdx.x) * 4;
    float4 v = *(const float4*)(A + i);
    uint32_t h0, l0, h1, l1;
    split_pair_f16(v.x, v.y, h0, l0);
    split_pair_f16(v.z, v.w, h1, l1);
    *(uint2*)(H + i) = make_uint2(h0, h1);
    *(uint2*)(L + i) = make_uint2(l0, l1);
}

// ---------------- weight prep: W[K][N] fp32 -> T[N][K] single fp16 ----------------
__global__ void prep_w(const float* __restrict__ W, __half* __restrict__ T, int K, int N)
{
    __shared__ float t[32][33];
    const int k0 = blockIdx.y * 32, n0 = blockIdx.x * 32;
    const int tx = threadIdx.x, ty = threadIdx.y;
#pragma unroll
    for (int r = 0; r < 4; r++)
        t[ty + 8*r][tx] = W[(size_t)(k0 + ty + 8*r) * N + n0 + tx];
    __syncthreads();
#pragma unroll
    for (int r = 0; r < 4; r++) {
        const int n = n0 + ty + 8*r, k = k0 + tx;
        T[(size_t)n * K + k] = __float2half_rn(t[tx][ty + 8*r]);
    }
}

// ---------------- fp16x2 mma.sync GEMM, 8 warps (2m x 4n), 4-stage ring ----------------
// C[M,N] = (Ah+Al)[M,K] @ fp16(B)[N,K]^T  via 2 MMAs per k16 (a_h*b + a_l*b)
// smem per stage: Ah/Al/B each [128 rows][32 fp16] pad 80B = 10240B -> 30720B
// EPI 1: bf16 hi/lo split to g_qkv* head-transposed (q scaled 1/8)
// EPI 2: fp32 C = acc + bias + res
// EPI 3: fp16 hi/lo split of relu(acc + bias)
#define GS_BUF   30720
#define SMEM_G   (4*GS_BUF)

template<int EPI>
__global__ __launch_bounds__(256, 1)
void f16_gemm(const __half* __restrict__ Ahi, const __half* __restrict__ Alo,
              const __half* __restrict__ Bf,
              float* __restrict__ C, const float* __restrict__ bias,
              const float* __restrict__ res, int N, int K,
              __nv_bfloat16* __restrict__ Qhi, __nv_bfloat16* __restrict__ Qlo,
              __half* __restrict__ Ohi, __half* __restrict__ Olo)
{
    extern __shared__ char smem[];
    const uint32_t sbase = smem_u32(smem);
    const int tid = threadIdx.x, wid = tid >> 5, lane = tid & 31;
    const int g = lane >> 2, t = lane & 3;
    const int wm = wid >> 2, wn = wid & 3;
    const int bm = blockIdx.y, bn = blockIdx.x;

    float c[4][4][4];
#pragma unroll
    for (int mt = 0; mt < 4; mt++)
#pragma unroll
        for (int nt = 0; nt < 4; nt++)
#pragma unroll
            for (int f = 0; f < 4; f++) c[mt][nt][f] = 0.f;

    auto cp_all = [&](int buf, int kb) {
#pragma unroll
        for (int j = 0; j < 6; j++) {
            const int cidx = tid + 256 * j;
            const int arr = cidx >> 9;      // 0:Ah 1:Al 2:B
            const int cc  = cidx & 511;
            const int row = cc >> 2, kc = cc & 3;
            const __half* gp = (arr == 0 ? Ahi : arr == 1 ? Alo : Bf);
            const int base = (arr < 2 ? bm : bn) * 128;
            const __half* src = gp + (size_t)(base + row) * K + kb * 32 + kc * 8;
            const uint32_t dst = sbase + buf * GS_BUF + arr * 10240 + row * 80 + kc * 16;
            asm volatile("cp.async.cg.shared.global [%0], [%1], 16;\n" :: "r"(dst), "l"(src));
        }
        asm volatile("cp.async.commit_group;\n");
    };

    const uint32_t a_off = (uint32_t)((wm * 64 + (lane & 15)) * 80 + ((lane >> 4) << 4));
    const uint32_t b_off = (uint32_t)((wn * 32 + ((lane >> 4) << 3) + (lane & 7)) * 80
                                      + (((lane >> 3) & 1) << 4));

    const int niter = K >> 5;
    cp_all(0, 0);
    if (niter > 1) cp_all(1, 1);
    if (niter > 2) cp_all(2, 2);

    for (int it = 0; it < niter; it++) {
        const int buf = it & 3;
        asm volatile("cp.async.wait_group 2;\n");
        __syncthreads();
        if (it + 3 < niter) cp_all((it + 3) & 3, it + 3);

        const uint32_t sb = sbase + buf * GS_BUF;
#pragma unroll
        for (int ks = 0; ks < 2; ks++) {
            uint32_t Ah[4][4], Al[4][4], Bv[2][4];
#pragma unroll
            for (int mt = 0; mt < 4; mt++) {
                const uint32_t aa = sb + a_off + mt * (16 * 80) + ks * 32;
                ldsm4(Ah[mt], aa);
                ldsm4(Al[mt], aa + 10240);
            }
#pragma unroll
            for (int ng = 0; ng < 2; ng++) {
                const uint32_t ba = sb + b_off + ng * (16 * 80) + ks * 32;
                ldsm4(Bv[ng], ba + 20480);
            }
#pragma unroll
            for (int mt = 0; mt < 4; mt++)
#pragma unroll
                for (int nt = 0; nt < 4; nt++) {
                    const uint32_t* bb = &Bv[nt >> 1][(nt & 1) * 2];
                    mma_f16(c[mt][nt], Ah[mt], bb);   // hi * b
                    mma_f16(c[mt][nt], Al[mt], bb);   // lo * b
                }
        }
    }

    // ---------------- epilogue ----------------
#pragma unroll
    for (int mt = 0; mt < 4; mt++) {
        const int r0 = bm * 128 + wm * 64 + mt * 16 + g;
#pragma unroll
        for (int nt = 0; nt < 4; nt++) {
            const int c0 = bn * 128 + wn * 32 + nt * 8 + t * 2;
#pragma unroll
            for (int half = 0; half < 2; half++) {
                const int r = r0 + half * 8;
                float v0 = c[mt][nt][half * 2], v1 = c[mt][nt][half * 2 + 1];
                if (EPI == 1) {
                    const int which = c0 >> 10, cm = c0 & 1023;
                    if (which == 0) { v0 *= 0.125f; v1 *= 0.125f; }
                    uint32_t hp, lp;
                    split_pair(v0, v1, hp, lp);
                    const size_t idx = (size_t)which * (NTOK * D_MODEL)
                        + (((size_t)((r >> 11) * NHEADS + (cm >> 6)) * SEQ + (r & 2047)) * DK + (cm & 63));
                    *(uint32_t*)(Qhi + idx) = hp;
                    *(uint32_t*)(Qlo + idx) = lp;
                } else if (EPI == 2) {
                    const float* rs = res + (size_t)r * N + c0;
                    C[(size_t)r * N + c0]     = v0 + bias[c0]     + rs[0];
                    C[(size_t)r * N + c0 + 1] = v1 + bias[c0 + 1] + rs[1];
                } else { // 3: relu -> fp16 hi/lo
                    float a0 = fmaxf(v0 + bias[c0], 0.f);
                    float a1 = fmaxf(v1 + bias[c0 + 1], 0.f);
                    uint32_t hp, lp;
                    split_pair_f16(a0, a1, hp, lp);
                    const size_t idx = (size_t)r * N + c0;
                    *(uint32_t*)(Ohi + idx) = hp;
                    *(uint32_t*)(Olo + idx) = lp;
                }
            }
        }
    }
}

// ---------------- FA2-style tensor-core attention (proven bf16x3; fp16 ctx out) ----------------
#define AQ_H   0
#define AQ_L   18432
#define AKV    36864
#define AKVBUF 36864
#define ATSMEM (36864 + 2*36864)

__global__ __launch_bounds__(256, 2)
void attn_mma(const __nv_bfloat16* __restrict__ qkvh, const __nv_bfloat16* __restrict__ qkvl,
              const int* __restrict__ mask,
              __half* __restrict__ ctxh, __half* __restrict__ ctxl)
{
    extern __shared__ char sm[];
    const uint32_t sb = smem_u32(sm);
    const int tid = threadIdx.x, w = tid >> 5, lane = tid & 31;
    const int g = lane >> 2, t = lane & 3;
    const int qb = blockIdx.x, h = blockIdx.y, b = blockIdx.z;
    const size_t hoff = ((size_t)(b * NHEADS + h)) * SEQ * DK;

    const __nv_bfloat16* qh = qkvh + hoff + (size_t)qb * 128 * DK;
    const __nv_bfloat16* ql = qkvl + hoff + (size_t)qb * 128 * DK;
    const __nv_bfloat16* kh = qkvh + (size_t)NTOK * D_MODEL + hoff;
    const __nv_bfloat16* kl = qkvl + (size_t)NTOK * D_MODEL + hoff;
    const __nv_bfloat16* vh = qkvh + (size_t)2 * NTOK * D_MODEL + hoff;
    const __nv_bfloat16* vl = qkvl + (size_t)2 * NTOK * D_MODEL + hoff;

#pragma unroll
    for (int j = 0; j < 8; j++) {
        const int cidx = tid + j * 256;
        const int arr = cidx >> 10, cc = cidx & 1023;
        const int row = cc >> 3, k8 = cc & 7;
        const __nv_bfloat16* src = (arr == 0 ? qh : ql) + row * DK + k8 * 8;
        *(uint4*)(sm + AQ_H + arr * 18432 + row * 144 + k8 * 16) = *(const uint4*)src;
    }

    auto prefetch_kv = [&](int buf, int kv0) {
#pragma unroll
        for (int j = 0; j < 8; j++) {
            const int cidx = tid + j * 256;
            const int arr = cidx >> 9, cc = cidx & 511;
            const int row = cc >> 3, k8 = cc & 7;
            const __nv_bfloat16* src =
                (arr == 0 ? kh : arr == 1 ? kl : arr == 2 ? vh : vl)
                + (size_t)(kv0 + row) * DK + k8 * 8;
            const uint32_t dst = sb + AKV + buf * AKVBUF + arr * 9216 + row * 144 + k8 * 16;
            asm volatile("cp.async.cg.shared.global [%0], [%1], 16;\n" :: "r"(dst), "l"(src));
        }
        asm volatile("cp.async.commit_group;\n");
    };

    prefetch_kv(0, 0);

    float m0 = -1e30f, m1 = -1e30f, l0 = 0.f, l1 = 0.f;
    float co[8][4];
#pragma unroll
    for (int nt = 0; nt < 8; nt++)
#pragma unroll
        for (int f = 0; f < 4; f++) co[nt][f] = 0.f;

    const uint32_t qa_off = (uint32_t)((w * 16 + (lane & 15)) * 144 + ((lane >> 4) << 4));
    const uint32_t kb_sub = (uint32_t)((((lane >> 4) << 3) + (lane & 7)) * 144
                                       + (((lane >> 3) & 1) << 4));
    const uint32_t vb_sub = (uint32_t)(((((lane >> 3) & 1) << 3) + (lane & 7)) * 144
                                       + ((lane >> 4) << 4));
    const int* mrow_base = mask + b * SEQ;

    for (int it = 0; it < SEQ / 64; it++) {
        const int buf = it & 1;
        const int kv0 = it * 64;
        asm volatile("cp.async.wait_group 0;\n");
        __syncthreads();
        if (it + 1 < SEQ / 64) prefetch_kv(buf ^ 1, kv0 + 64);

        const uint32_t kvb = sb + AKV + buf * AKVBUF;

        float cs[8][4];
#pragma unroll
        for (int nt = 0; nt < 8; nt++)
#pragma unroll
            for (int f = 0; f < 4; f++) cs[nt][f] = 0.f;
#pragma unroll
        for (int ks = 0; ks < 4; ks++) {
            uint32_t Qh_[4], Ql_[4];
            const uint32_t aa = sb + qa_off + ks * 32;
            ldsm4(Qh_, aa + AQ_H);
            ldsm4(Ql_, aa + AQ_L);
#pragma unroll
            for (int ng = 0; ng < 4; ng++) {
                uint32_t Kh_[4], Kl_[4];
                const uint32_t ba = kvb + ng * (16 * 144) + kb_sub + ks * 32;
                ldsm4(Kh_, ba);
                ldsm4(Kl_, ba + 9216);
#pragma unroll
                for (int h2 = 0; h2 < 2; h2++) {
                    const int nt = ng * 2 + h2;
                    mma_bf16(cs[nt], Qh_, &Kh_[h2 * 2]);
                    mma_bf16(cs[nt], Qh_, &Kl_[h2 * 2]);
                    mma_bf16(cs[nt], Ql_, &Kh_[h2 * 2]);
                }
            }
        }

#pragma unroll
        for (int nt = 0; nt < 8; nt++) {
            int2 mv = *(const int2*)(mrow_base + kv0 + nt * 8 + t * 2);
            if (mv.x == 0) { cs[nt][0] = -1e9f; cs[nt][2] = -1e9f; }
            if (mv.y == 0) { cs[nt][1] = -1e9f; cs[nt][3] = -1e9f; }
        }
        float mx0 = cs[0][0], mx1 = cs[0][2];
#pragma unroll
        for (int nt = 0; nt < 8; nt++) {
            mx0 = fmaxf(mx0, fmaxf(cs[nt][0], cs[nt][1]));
            mx1 = fmaxf(mx1, fmaxf(cs[nt][2], cs[nt][3]));
        }
        mx0 = fmaxf(mx0, __shfl_xor_sync(0xffffffffu, mx0, 1));
        mx0 = fmaxf(mx0, __shfl_xor_sync(0xffffffffu, mx0, 2));
        mx1 = fmaxf(mx1, __shfl_xor_sync(0xffffffffu, mx1, 1));
        mx1 = fmaxf(mx1, __shfl_xor_sync(0xffffffffu, mx1, 2));
        const float mn0 = fmaxf(m0, mx0), mn1 = fmaxf(m1, mx1);
        const float f0 = fexp(m0 - mn0), f1 = fexp(m1 - mn1);
        m0 = mn0; m1 = mn1;

        uint32_t phg[8], phg8[8], plg[8], plg8[8];
        float rs0 = 0.f, rs1 = 0.f;
#pragma unroll
        for (int nt = 0; nt < 8; nt++) {
            float p0 = fexp(cs[nt][0] - mn0);
            float p1 = fexp(cs[nt][1] - mn0);
            float p2 = fexp(cs[nt][2] - mn1);
            float p3 = fexp(cs[nt][3] - mn1);
            rs0 += p0 + p1; rs1 += p2 + p3;
            split_pair(p0, p1, phg[nt], plg[nt]);
            split_pair(p2, p3, phg8[nt], plg8[nt]);
        }
        rs0 += __shfl_xor_sync(0xffffffffu, rs0, 1);
        rs0 += __shfl_xor_sync(0xffffffffu, rs0, 2);
        rs1 += __shfl_xor_sync(0xffffffffu, rs1, 1);
        rs1 += __shfl_xor_sync(0xffffffffu, rs1, 2);
        l0 = l0 * f0 + rs0;
        l1 = l1 * f1 + rs1;

#pragma unroll
        for (int nt = 0; nt < 8; nt++) {
            co[nt][0] *= f0; co[nt][1] *= f0;
            co[nt][2] *= f1; co[nt][3] *= f1;
        }

#pragma unroll
        for (int kc = 0; kc < 4; kc++) {
            uint32_t Ah[4] = { phg[2*kc], phg8[2*kc], phg[2*kc+1], phg8[2*kc+1] };
            uint32_t Al[4] = { plg[2*kc], plg8[2*kc], plg[2*kc+1], plg8[2*kc+1] };
#pragma unroll
            for (int ng = 0; ng < 4; ng++) {
                uint32_t Vh_[4], Vl_[4];
                const uint32_t va = kvb + 18432 + kc * (16 * 144) + vb_sub + ng * 32;
                ldsm4t(Vh_, va);
                ldsm4t(Vl_, va + 9216);
#pragma unroll
                for (int h2 = 0; h2 < 2; h2++) {
                    const int nt = ng * 2 + h2;
                    mma_bf16(co[nt], Ah, &Vh_[h2 * 2]);
                    mma_bf16(co[nt], Ah, &Vl_[h2 * 2]);
                    mma_bf16(co[nt], Al, &Vh_[h2 * 2]);
                }
            }
        }
    }

    const float inv0 = 1.0f / l0, inv1 = 1.0f / l1;
    const int r0 = qb * 128 + w * 16 + g;
    const size_t base0 = ((size_t)(b * SEQ + r0)) * D_MODEL + h * 64;
    const size_t base1 = ((size_t)(b * SEQ + r0 + 8)) * D_MODEL + h * 64;
#pragma unroll
    for (int nt = 0; nt < 8; nt++) {
        const int col = nt * 8 + t * 2;
        uint32_t hp, lp;
        split_pair_f16(co[nt][0] * inv0, co[nt][1] * inv0, hp, lp);
        *(uint32_t*)(ctxh + base0 + col) = hp;
        *(uint32_t*)(ctxl + base0 + col) = lp;
        split_pair_f16(co[nt][2] * inv1, co[nt][3] * inv1, hp, lp);
        *(uint32_t*)(ctxh + base1 + col) = hp;
        *(uint32_t*)(ctxl + base1 + col) = lp;
    }
}

// ---------------- LayerNorm (ddof=1, eps added to std); optional fp16 hi/lo out ----------------
__device__ __forceinline__ float warp_sum(float s) {
#pragma unroll
    for (int off = 16; off; off >>= 1) s += __shfl_xor_sync(0xffffffffu, s, off);
    return s;
}

__global__ __launch_bounds__(256)
void ln_kernel(const float* __restrict__ in, const float* __restrict__ alpha,
               const float* __restrict__ beta, float* __restrict__ out,
               __half* __restrict__ outh, __half* __restrict__ outl)
{
    __shared__ float red[8];
    const int row = blockIdx.x, tid = threadIdx.x;
    const float* rp = in + (size_t)row * D_MODEL;
    float4 v = *(const float4*)(rp + tid*4);

    float s = v.x + v.y + v.z + v.w;
    s = warp_sum(s);
    if ((tid & 31) == 0) red[tid >> 5] = s;
    __syncthreads();
    float tot = 0.f;
#pragma unroll
    for (int i = 0; i < 8; i++) tot += red[i];
    float mean = tot * (1.0f / 1024.0f);

    float dx = v.x - mean, dy = v.y - mean, dz = v.z - mean, dw = v.w - mean;
    float sq = dx*dx + dy*dy + dz*dz + dw*dw;
    __syncthreads();
    sq = warp_sum(sq);
    if ((tid & 31) == 0) red[tid >> 5] = sq;
    __syncthreads();
    float tot2 = 0.f;
#pragma unroll
    for (int i = 0; i < 8; i++) tot2 += red[i];
    float var  = tot2 * (1.0f / 1023.0f);
    float rstd = 1.0f / (sqrtf(var) + 1e-6f);

    float4 a = *(const float4*)(alpha + tid*4);
    float4 bb = *(const float4*)(beta + tid*4);
    float4 o;
    o.x = a.x * dx * rstd + bb.x;
    o.y = a.y * dy * rstd + bb.y;
    o.z = a.z * dz * rstd + bb.z;
    o.w = a.w * dw * rstd + bb.w;
    *(float4*)(out + (size_t)row * D_MODEL + tid*4) = o;
    if (outh) {
        uint32_t h0, l0, h1, l1;
        split_pair_f16(o.x, o.y, h0, l0);
        split_pair_f16(o.z, o.w, h1, l1);
        *(uint2*)(outh + (size_t)row * D_MODEL + tid*4) = make_uint2(h0, h1);
        *(uint2*)(outl + (size_t)row * D_MODEL + tid*4) = make_uint2(l0, l1);
    }
}

// ---------------- host ----------------
extern "C" void kernel_launch(void* const* d_in, const int* in_sizes, int n_in,
                              void* d_out, int out_size)
{
    const float* x      = (const float*)d_in[0];
    const int*   mask   = (const int*)  d_in[1];
    const float* wq     = (const float*)d_in[2];
    const float* wk     = (const float*)d_in[3];
    const float* wv     = (const float*)d_in[4];
    const float* wo     = (const float*)d_in[5];
    const float* wo_b   = (const float*)d_in[6];
    const float* w1     = (const float*)d_in[7];
    const float* b1     = (const float*)d_in[8];
    const float* w2     = (const float*)d_in[9];
    const float* b2     = (const float*)d_in[10];
    const float* alpha1 = (const float*)d_in[11];
    const float* bias1  = (const float*)d_in[12];
    const float* alpha2 = (const float*)d_in[13];
    const float* bias2  = (const float*)d_in[14];
    float* out = (float*)d_out;

    float *s1, *x1, *s2;
    __half *xh, *xl, *ctxh, *ctxl, *x1h, *x1l, *ffh, *ffl;
    __nv_bfloat16 *qkvh, *qkvl;
    __half *wqkv_f, *wo_f, *w1_f, *w2_f;
    cudaGetSymbolAddress((void**)&s1,  g_s1);
    cudaGetSymbolAddress((void**)&x1,  g_x1);
    cudaGetSymbolAddress((void**)&s2,  g_s2);
    cudaGetSymbolAddress((void**)&xh,  g_xh);   cudaGetSymbolAddress((void**)&xl,  g_xl);
    cudaGetSymbolAddress((void**)&qkvh, g_qkvh); cudaGetSymbolAddress((void**)&qkvl, g_qkvl);
    cudaGetSymbolAddress((void**)&ctxh, g_ctxh); cudaGetSymbolAddress((void**)&ctxl, g_ctxl);
    cudaGetSymbolAddress((void**)&x1h, g_x1h);  cudaGetSymbolAddress((void**)&x1l, g_x1l);
    cudaGetSymbolAddress((void**)&ffh, g_ffh);  cudaGetSymbolAddress((void**)&ffl, g_ffl);
    cudaGetSymbolAddress((void**)&wqkv_f, g_wqkv_f);
    cudaGetSymbolAddress((void**)&wo_f, g_wo_f);
    cudaGetSymbolAddress((void**)&w1_f, g_w1_f);
    cudaGetSymbolAddress((void**)&w2_f, g_w2_f);

    // idempotent; no static guards allowed
    cudaFuncSetAttribute(f16_gemm<1>, cudaFuncAttributeMaxDynamicSharedMemorySize, SMEM_G);
    cudaFuncSetAttribute(f16_gemm<2>, cudaFuncAttributeMaxDynamicSharedMemorySize, SMEM_G);
    cudaFuncSetAttribute(f16_gemm<3>, cudaFuncAttributeMaxDynamicSharedMemorySize, SMEM_G);
    cudaFuncSetAttribute(attn_mma,    cudaFuncAttributeMaxDynamicSharedMemorySize, ATSMEM);

    dim3 tblk(32, 8);
    prep_w<<<dim3(D_MODEL/32, D_MODEL/32), tblk>>>(wq, wqkv_f,                     D_MODEL, D_MODEL);
    prep_w<<<dim3(D_MODEL/32, D_MODEL/32), tblk>>>(wk, wqkv_f + D_MODEL*D_MODEL,   D_MODEL, D_MODEL);
    prep_w<<<dim3(D_MODEL/32, D_MODEL/32), tblk>>>(wv, wqkv_f + 2*D_MODEL*D_MODEL, D_MODEL, D_MODEL);
    prep_w<<<dim3(D_MODEL/32, D_MODEL/32), tblk>>>(wo, wo_f, D_MODEL, D_MODEL);
    prep_w<<<dim3(DFF/32,     D_MODEL/32), tblk>>>(w1, w1_f, D_MODEL, DFF);
    prep_w<<<dim3(D_MODEL/32, DFF/32),     tblk>>>(w2, w2_f, DFF, D_MODEL);

    // split x once (fp16 hi/lo)
    xsplit<<<(NTOK*D_MODEL)/1024, 256>>>(x, xh, xl);

    // fused QKV projection (N=3072) -> bf16 hi/lo head-transposed, q pre-scaled
    f16_gemm<1><<<dim3(24, 32), 256, SMEM_G>>>(xh, xl, wqkv_f,
                                               nullptr, nullptr, nullptr, 3*D_MODEL, D_MODEL,
                                               qkvh, qkvl, nullptr, nullptr);

    attn_mma<<<dim3(SEQ/128, NHEADS, BATCH), 256, ATSMEM>>>(qkvh, qkvl, mask, ctxh, ctxl);

    // O projection + residual, LN1 (LN emits fp16 for FFN1 A)
    f16_gemm<2><<<dim3(8, 32), 256, SMEM_G>>>(ctxh, ctxl, wo_f,
                                              s1, wo_b, x, D_MODEL, D_MODEL,
                                              nullptr, nullptr, nullptr, nullptr);
    ln_kernel<<<NTOK, 256>>>(s1, alpha1, bias1, x1, x1h, x1l);

    // FFN
    f16_gemm<3><<<dim3(32, 32), 256, SMEM_G>>>(x1h, x1l, w1_f,
                                               nullptr, b1, nullptr, DFF, D_MODEL,
                                               nullptr, nullptr, ffh, ffl);
    f16_gemm<2><<<dim3(8, 32), 256, SMEM_G>>>(ffh, ffl, w2_f,
                                              s2, b2, x1, D_MODEL, DFF,
                                              nullptr, nullptr, nullptr, nullptr);
    ln_kernel<<<NTOK, 256>>>(s2, alpha2, bias2, out, nullptr, nullptr);
}